// round 5
// baseline (speedup 1.0000x reference)
#include <cuda_runtime.h>
#include <cstdint>

constexpr int T = 512, B = 64, F = 32, K = 32;

constexpr int OFF_SCORE = 0;
constexpr int OFF_MAXS  = 64;                    // [T,B,K]
constexpr int OFF_IDX   = 64 + T * B * K;        // [T,B,K]
constexpr int OFF_FEATS = 64 + 2 * T * B * K;    // [T,B,K]

#define FULL 0xffffffffu
#define VOLI(x) (*(volatile int*)&(x))

__device__ __forceinline__ float ex2f(float x) {
    float y; asm("ex2.approx.f32 %0, %1;" : "=f"(y) : "f"(x)); return y;
}
__device__ __forceinline__ float lg2f(float x) {
    float y; asm("lg2.approx.f32 %0, %1;" : "=f"(y) : "f"(x)); return y;
}

constexpr float L2E  = 1.4426950408889634f;
constexpr float LN2  = 0.6931471805599453f;
constexpr float LN32 = 3.4657359027997265f;

constexpr int NPROD = 8;      // producer warps (wid 4..11)
constexpr int FR    = 64;     // feats ring depth (steps)

// One persistent block per batch:
//   wid 0      : forward chain (linear domain)   -> forward_score[b]
//   wid 1      : Viterbi chain                   -> max_s[1..511]
//   wid 2,3    : backpointer consumers           -> max_s_idx[1..511]
//   wid 4..11  : feats producers (gather+sum)    -> feats[:], max_s[0], idx[0]
__global__ void __launch_bounds__(384, 1)
crf_fused(const int* __restrict__ words, const int* __restrict__ lens,
          const float* __restrict__ W, const float* __restrict__ trans,
          float* out)
{
    __shared__ float fring[FR][K];     // feats ring
    __shared__ int   s_prog[NPROD];    // producer p: all rows t<=s_prog[p], t%NPROD==p done
    __shared__ int   s_cons[2];        // fwd / vit completed step (back-pressure)
    __shared__ int   s_vw;             // vit watermark: maxs[<=s_vw] visible
    __shared__ int   s_bp[2];          // bp warp progress

    int tid  = threadIdx.x;
    int wid  = tid >> 5;
    int lane = tid & 31;
    int b    = blockIdx.x;

    if (tid < NPROD) s_prog[tid] = -1;
    if (tid < 2)     { s_cons[tid] = 0; s_bp[tid] = 0; }
    if (tid == 0)    s_vw = -1;
    __syncthreads();

    int L = __ldg(&lens[b]);

    if (wid >= 4) {
        // ================= producers: emission feats =================
        int p = wid - 4;
        for (int t = p; t < T; t += NPROD) {
            if (t >= FR) {  // don't overwrite a slot the chains may still read
                while (min(VOLI(s_cons[0]), VOLI(s_cons[1])) < t - FR + 8)
                    __nanosleep(40);
            }
            bool valid = (t < L);
            int gw = t * B + b;
            int w = valid ? __ldg(&words[gw * F + lane]) : 0;
            float s0 = 0.f, s1 = 0.f, s2 = 0.f, s3 = 0.f;
#pragma unroll
            for (int f = 0; f < F; f += 4) {
                int w0 = __shfl_sync(FULL, w, f);
                int w1 = __shfl_sync(FULL, w, f + 1);
                int w2 = __shfl_sync(FULL, w, f + 2);
                int w3 = __shfl_sync(FULL, w, f + 3);
                int i0 = valid ? (w0 + lane) : 0;   // mask AFTER tag shift
                int i1 = valid ? (w1 + lane) : 0;
                int i2 = valid ? (w2 + lane) : 0;
                int i3 = valid ? (w3 + lane) : 0;
                s0 += __ldg(&W[i0]); s1 += __ldg(&W[i1]);
                s2 += __ldg(&W[i2]); s3 += __ldg(&W[i3]);
            }
            float s = (s0 + s1) + (s2 + s3);
            out[OFF_FEATS + gw * K + lane] = s;
            if (t == 0) {
                out[OFF_MAXS + b * K + lane] = s;    // max_s[0]
                out[OFF_IDX  + b * K + lane] = 0.f;  // max_s_idx[0]
            }
            fring[t & (FR - 1)][lane] = s;
            __syncwarp();
            __threadfence_block();
            __syncwarp();
            if (lane == 0) VOLI(s_prog[p]) = t;
        }
        __syncwarp();
        if (lane == 0) VOLI(s_prog[p]) = T;          // final release

    } else if (wid == 0) {
        // ================= forward chain (linear domain) =================
        float et[K];
#pragma unroll
        for (int j = 0; j < K; j++) et[j] = ex2f(__ldg(&trans[j * K + lane]) * L2E);

        // wait for rows 0..19 (prologue + first 16-step block)
        {
            volatile int* sp = s_prog;
            for (;;) {
                int m = sp[0];
#pragma unroll
                for (int i = 1; i < NPROD; i++) m = min(m, sp[i]);
                if (m >= 19) break;
            }
            __threadfence_block();
        }
        float f0 = fring[0][lane];
        float C0 = __shfl_sync(FULL, f0, 0);
        float E  = ex2f((f0 - C0) * L2E);
        float Ctot = C0;

        float fA = fring[1][lane], fB = fring[2][lane], fC = fring[3][lane];
        float xA = ex2f(fA * L2E - 5.f);
        float xB = ex2f(fB * L2E - 5.f);

        for (int base = 1; base < T; base += 16) {
            int end = min(base + 15, T - 1);
            int lim = min(end + 3, T - 1);
            {
                volatile int* sp = s_prog;
                for (;;) {
                    int m = sp[0];
#pragma unroll
                    for (int i = 1; i < NPROD; i++) m = min(m, sp[i]);
                    if (m >= lim) break;
                }
                __threadfence_block();
            }
            for (int t = base; t <= end; t++) {
                float xf = xA;
                xA = xB;
                fA = fB; fB = fC;
                int tp = (t + 3 > T - 1) ? (T - 1) : (t + 3);
                fC = fring[tp & (FR - 1)][lane];
                xB = ex2f(fB * L2E - 5.f);

                float s0 = 0.f, s1 = 0.f, s2 = 0.f, s3 = 0.f;
#pragma unroll
                for (int j = 0; j < K; j += 4) {
                    s0 = fmaf(__shfl_sync(FULL, E, j),     et[j],     s0);
                    s1 = fmaf(__shfl_sync(FULL, E, j + 1), et[j + 1], s1);
                    s2 = fmaf(__shfl_sync(FULL, E, j + 2), et[j + 2], s2);
                    s3 = fmaf(__shfl_sync(FULL, E, j + 3), et[j + 3], s3);
                }
                float S  = (s0 + s1) + (s2 + s3);
                float En = S * xf;                       // * exp(f_k)/32
                if (t < L) { E = En; Ctot += LN32; }     // freeze on pad

                if ((t & 31) == 0) {                     // renorm (alpha-preserving)
                    float r = __shfl_sync(FULL, E, 0);
                    float c = lg2f(r);
                    E *= ex2f(-c);
                    Ctot += c * LN2;
                }
            }
            __syncwarp();
            if (lane == 0) VOLI(s_cons[0]) = end;
        }
        float e = E;
#pragma unroll
        for (int o = 16; o; o >>= 1) e += __shfl_xor_sync(FULL, e, o);
        if (lane == 0) out[OFF_SCORE + b] = Ctot + lg2f(e) * LN2;
        __syncwarp();
        if (lane == 0) VOLI(s_cons[0]) = T + FR;

    } else if (wid == 1) {
        // ================= Viterbi chain =================
        float tc[K];
#pragma unroll
        for (int j = 0; j < K; j++) tc[j] = __ldg(&trans[j * K + lane]);

        {
            volatile int* sp = s_prog;
            for (;;) {
                int m = sp[0];
#pragma unroll
                for (int i = 1; i < NPROD; i++) m = min(m, sp[i]);
                if (m >= 19) break;
            }
            __threadfence_block();
        }
        float delta = fring[0][lane];
        if (lane == 0) VOLI(s_vw) = 0;    // maxs[0] written+fenced by producer 0

        float fA = fring[1][lane], fB = fring[2][lane], fC = fring[3][lane];

        for (int base = 1; base < T; base += 16) {
            int end = min(base + 15, T - 1);
            int lim = min(end + 3, T - 1);
            {
                volatile int* sp = s_prog;
                for (;;) {
                    int m = sp[0];
#pragma unroll
                    for (int i = 1; i < NPROD; i++) m = min(m, sp[i]);
                    if (m >= lim) break;
                }
                __threadfence_block();
            }
            if (base > 24) {   // bp back-pressure (ring is global maxs; just bound lag)
                while (min(VOLI(s_bp[0]), VOLI(s_bp[1])) < base - 24)
                    __nanosleep(40);
            }
            for (int t = base; t <= end; t++) {
                float f = fA;
                fA = fB; fB = fC;
                int tp = (t + 3 > T - 1) ? (T - 1) : (t + 3);
                fC = fring[tp & (FR - 1)][lane];

                const float NEG_INF = __int_as_float(0xff800000);
                float m0 = NEG_INF, m1 = NEG_INF, m2 = NEG_INF, m3 = NEG_INF;
#pragma unroll
                for (int j = 0; j < K; j += 4) {
                    m0 = fmaxf(m0, __shfl_sync(FULL, delta, j)     + tc[j]);
                    m1 = fmaxf(m1, __shfl_sync(FULL, delta, j + 1) + tc[j + 1]);
                    m2 = fmaxf(m2, __shfl_sync(FULL, delta, j + 2) + tc[j + 2]);
                    m3 = fmaxf(m3, __shfl_sync(FULL, delta, j + 3) + tc[j + 3]);
                }
                float dnew = fmaxf(fmaxf(m0, m1), fmaxf(m2, m3)) + f;
                if (t < L) delta = dnew;                     // freeze on pad
                out[OFF_MAXS + (t * B + b) * K + lane] = delta;

                if ((t & 7) == 0) {                          // publish to bp warps
                    __syncwarp();
                    __threadfence_block();
                    __syncwarp();
                    if (lane == 0) VOLI(s_vw) = t;
                }
            }
            __syncwarp();
            if (lane == 0) VOLI(s_cons[1]) = end;
        }
        __syncwarp();
        __threadfence_block();
        __syncwarp();
        if (lane == 0) { VOLI(s_vw) = T; VOLI(s_cons[1]) = T + FR; }

    } else {
        // ================= backpointer consumers (wid 2,3) =================
        int q = wid - 2;
        float tcj[K];
#pragma unroll
        for (int j = 0; j < K; j++) tcj[j] = __ldg(&trans[j * K + lane]);

        for (int t = 1 + q; t < T; t += 2) {
            while (VOLI(s_vw) < t - 1) __nanosleep(30);
            __threadfence_block();
            float dp = out[OFF_MAXS + ((t - 1) * B + b) * K + lane];

            float best = __shfl_sync(FULL, dp, 0) + tcj[0];
            int   bi   = 0;
#pragma unroll
            for (int j = 1; j < K; j++) {
                float sc = __shfl_sync(FULL, dp, j) + tcj[j];
                if (sc > best) { best = sc; bi = j; }   // strict > keeps first
            }
            out[OFF_IDX + (t * B + b) * K + lane] = (float)bi;

            if ((t & 15) <= 1) {
                __syncwarp();
                if (lane == 0) VOLI(s_bp[q]) = t;
            }
        }
        __syncwarp();
        if (lane == 0) VOLI(s_bp[q]) = T + FR;
    }
}

// ---------------------------------------------------------------------------
extern "C" void kernel_launch(void* const* d_in, const int* in_sizes, int n_in,
                              void* d_out, int out_size) {
    const int*   words = (const int*)d_in[0];     // [T,B,F] int32
    const int*   lens  = (const int*)d_in[1];     // [B] int32
    const float* W     = (const float*)d_in[2];   // [1e6] f32
    const float* trans = (const float*)d_in[3];   // [K,K] f32
    float* out = (float*)d_out;

    crf_fused<<<B, 384>>>(words, lens, W, trans, out);
}

// round 7
// speedup vs baseline: 1.2398x; 1.2398x over previous
#include <cuda_runtime.h>
#include <cstdint>

constexpr int T = 512, B = 64, F = 32, K = 32;

constexpr int OFF_SCORE = 0;
constexpr int OFF_MAXS  = 64;                    // [T,B,K]
constexpr int OFF_IDX   = 64 + T * B * K;        // [T,B,K]
constexpr int OFF_FEATS = 64 + 2 * T * B * K;    // [T,B,K]

#define FULL 0xffffffffu
#define VOLI(x) (*(volatile int*)&(x))

__device__ __forceinline__ float ex2f(float x) {
    float y; asm("ex2.approx.f32 %0, %1;" : "=f"(y) : "f"(x)); return y;
}
__device__ __forceinline__ float lg2f(float x) {
    float y; asm("lg2.approx.f32 %0, %1;" : "=f"(y) : "f"(x)); return y;
}
__device__ __forceinline__ uint32_t s2u(const void* p) {
    uint32_t a;
    asm("{ .reg .u64 t; cvta.to.shared.u64 t, %1; cvt.u32.u64 %0, t; }"
        : "=r"(a) : "l"(p));
    return a;
}

constexpr float L2E  = 1.4426950408889634f;
constexpr float LN2  = 0.6931471805599453f;
constexpr float LN32 = 3.4657359027997265f;

// ---------------------------------------------------------------------------
// Kernel 1: emission feats.  One warp per (t,b); lane = tag k.
// ---------------------------------------------------------------------------
__global__ void feats_kernel(const int* __restrict__ words,
                             const int* __restrict__ lens,
                             const float* __restrict__ W,
                             float* __restrict__ feats,
                             float* __restrict__ maxs,
                             float* __restrict__ idxo) {
    int gw   = (blockIdx.x * blockDim.x + threadIdx.x) >> 5;   // t*B + b
    int lane = threadIdx.x & 31;
    if (gw >= T * B) return;
    int t = gw >> 6;
    int b = gw & 63;

    int L = __ldg(&lens[b]);
    bool valid = (t < L);

    int w = valid ? __ldg(&words[gw * F + lane]) : 0;

    float s0 = 0.f, s1 = 0.f, s2 = 0.f, s3 = 0.f;
#pragma unroll
    for (int f = 0; f < F; f += 4) {
        int w0 = __shfl_sync(FULL, w, f);
        int w1 = __shfl_sync(FULL, w, f + 1);
        int w2 = __shfl_sync(FULL, w, f + 2);
        int w3 = __shfl_sync(FULL, w, f + 3);
        int i0 = valid ? (w0 + lane) : 0;   // mask AFTER tag shift (ref semantics)
        int i1 = valid ? (w1 + lane) : 0;
        int i2 = valid ? (w2 + lane) : 0;
        int i3 = valid ? (w3 + lane) : 0;
        s0 += __ldg(&W[i0]); s1 += __ldg(&W[i1]);
        s2 += __ldg(&W[i2]); s3 += __ldg(&W[i3]);
    }
    float s = (s0 + s1) + (s2 + s3);

    feats[gw * K + lane] = s;
    if (t == 0) {
        maxs[b * K + lane] = s;     // max_s[0] = feats[0]
        idxo[b * K + lane] = 0.f;   // max_s_idx[0] = 0
    }
}

// ---------------------------------------------------------------------------
// Kernel 2: recurrence + backpointers.  One block per batch, 4 warps:
//   wid 3: Viterbi chain (top arbiter priority)  -> max_s[1..]
//   wid 2: forward chain (linear domain)         -> forward_score[b]
//   wid 0,1: backpointer consumers trailing wid3 -> max_s_idx[1..]
// feats streamed into smem in 128-step chunks via cp.async (double buffer).
// ---------------------------------------------------------------------------
__global__ void __launch_bounds__(128, 1)
rec_kernel(const float* __restrict__ trans,
           const int* __restrict__ lens,
           const float* __restrict__ feats,
           float* __restrict__ maxs,
           float* __restrict__ idxo,
           float* __restrict__ score) {
    __shared__ __align__(16) float sf[2][128][K];   // 32 KB feats double buffer
    __shared__ int s_vw;                             // maxs[<=s_vw] visible

    int tid  = threadIdx.x;
    int wid  = tid >> 5;
    int lane = tid & 31;
    int b    = blockIdx.x;

    if (tid == 0) s_vw = 0;           // maxs[0] written by feats_kernel
    __syncthreads();

    int L = __ldg(&lens[b]);          // uniform within block

    float tc[K];
#pragma unroll
    for (int j = 0; j < K; j++) tc[j] = __ldg(&trans[j * K + lane]);

    if (wid >= 2) {
        // ================= chain warps (wid 2 fwd, wid 3 vit) =================
        int ct = tid - 64;            // 0..63 cooperative index

        auto issue_chunk = [&](int c) {
            const float* base = feats + (c * 128) * (B * K) + b * K;
#pragma unroll
            for (int i = 0; i < 16; i++) {
                int op  = ct + 64 * i;          // 0..1023
                int row = op >> 3, seg = op & 7;
                const float* src = base + row * (B * K) + seg * 4;
                uint32_t dst = s2u(&sf[c & 1][row][seg * 4]);
                asm volatile("cp.async.ca.shared.global [%0], [%1], 16;"
                             :: "r"(dst), "l"(src));
            }
            asm volatile("cp.async.commit_group;");
        };

        issue_chunk(0);
        issue_chunk(1);
        asm volatile("cp.async.wait_group 1;");      // chunk 0 ready
        asm volatile("bar.sync 1, 64;");             // chain warps only

        float f0 = sf[0][0][lane];
        bool isF = (wid == 2);

        // per-role state
        float et[K];
        float E = 0.f, Ctot = 0.f, delta = 0.f;
        if (isF) {
#pragma unroll
            for (int j = 0; j < K; j++) et[j] = ex2f(tc[j] * L2E);
            float C0 = __shfl_sync(FULL, f0, 0);
            E    = ex2f((f0 - C0) * L2E);
            Ctot = C0;
        } else {
            delta = f0;
        }

        bool done = false;
        for (int c = 0; c < 4 && !done; c++) {
            const float (*fb)[K] = sf[c & 1];
            int r0 = (c == 0) ? 1 : 0;
#pragma unroll 2
            for (int r = r0; r < 128; r++) {
                int t = c * 128 + r;
                if (t >= L) { done = true; break; }
                float f = fb[r][lane];

                if (isF) {
                    float s0 = 0.f, s1 = 0.f, s2 = 0.f, s3 = 0.f;
#pragma unroll
                    for (int j = 0; j < K; j += 4) {
                        s0 = fmaf(__shfl_sync(FULL, E, j),     et[j],     s0);
                        s1 = fmaf(__shfl_sync(FULL, E, j + 1), et[j + 1], s1);
                        s2 = fmaf(__shfl_sync(FULL, E, j + 2), et[j + 2], s2);
                        s3 = fmaf(__shfl_sync(FULL, E, j + 3), et[j + 3], s3);
                    }
                    float S  = (s0 + s1) + (s2 + s3);
                    float xf = ex2f(fmaf(f, L2E, -5.f));     // exp(f)/32
                    E = S * xf;
                    Ctot += LN32;
                    if ((t & 127) == 0) {                    // renorm (alpha-preserving)
                        float rr = __shfl_sync(FULL, E, 0);
                        float cc = lg2f(rr);
                        E *= ex2f(-cc);
                        Ctot += cc * LN2;
                    }
                } else {
                    const float NEG_INF = __int_as_float(0xff800000);
                    float m0 = NEG_INF, m1 = NEG_INF, m2 = NEG_INF, m3 = NEG_INF;
#pragma unroll
                    for (int j = 0; j < K; j += 4) {
                        m0 = fmaxf(m0, __shfl_sync(FULL, delta, j)     + tc[j]);
                        m1 = fmaxf(m1, __shfl_sync(FULL, delta, j + 1) + tc[j + 1]);
                        m2 = fmaxf(m2, __shfl_sync(FULL, delta, j + 2) + tc[j + 2]);
                        m3 = fmaxf(m3, __shfl_sync(FULL, delta, j + 3) + tc[j + 3]);
                    }
                    delta = fmaxf(fmaxf(m0, m1), fmaxf(m2, m3)) + f;
                    maxs[(t * B + b) * K + lane] = delta;
                    if ((t & 15) == 0) {                     // publish to bp warps
                        __syncwarp();
                        __threadfence_block();
                        if (lane == 0) VOLI(s_vw) = t;
                        __syncwarp();
                    }
                }
            }
            if (!done && c < 3) {
                asm volatile("cp.async.wait_group 0;");      // next chunk ready
                asm volatile("bar.sync 1, 64;");
                if (c < 2) issue_chunk(c + 2);
            }
        }
        asm volatile("cp.async.wait_group 0;");              // drain

        if (isF) {
            float e = E;
#pragma unroll
            for (int o = 16; o; o >>= 1) e += __shfl_xor_sync(FULL, e, o);
            if (lane == 0) score[b] = Ctot + lg2f(e) * LN2;
        } else {
            // frozen tail: max_s[t] = delta for t in [L, T)
#pragma unroll 4
            for (int t = L; t < T; t++)
                maxs[(t * B + b) * K + lane] = delta;
            __syncwarp();
            __threadfence_block();
            if (lane == 0) VOLI(s_vw) = T;                   // final release
        }

    } else {
        // ================= backpointer warps (wid 0,1) =================
        int q = wid;                                  // handles t with t%2 == (1+q)%2
        int Lc = (L < T) ? L : T;

        for (int t = 1 + q; t < Lc; t += 2) {
            while (VOLI(s_vw) < t - 1) __nanosleep(32);
            __threadfence_block();
            float dp = maxs[((t - 1) * B + b) * K + lane];

            float best = __shfl_sync(FULL, dp, 0) + tc[0];
            int   bi   = 0;
#pragma unroll
            for (int j = 1; j < K; j++) {
                float sc = __shfl_sync(FULL, dp, j) + tc[j];
                if (sc > best) { best = sc; bi = j; }  // strict > keeps first index
            }
            idxo[(t * B + b) * K + lane] = (float)bi;
        }

        if (L < T) {
            // frozen region: bp constant, computed once from maxs[L-1]
            while (VOLI(s_vw) < L - 1) __nanosleep(32);
            __threadfence_block();
            float dp = maxs[((L - 1) * B + b) * K + lane];

            float best = __shfl_sync(FULL, dp, 0) + tc[0];
            int   bi   = 0;
#pragma unroll
            for (int j = 1; j < K; j++) {
                float sc = __shfl_sync(FULL, dp, j) + tc[j];
                if (sc > best) { best = sc; bi = j; }
            }
            float v = (float)bi;
            int t0 = L + (((1 + q) - L) & 1);          // first t>=L with right parity
            if (t0 < 1 + q) t0 = 1 + q;
#pragma unroll 4
            for (int t = t0; t < T; t += 2)
                idxo[(t * B + b) * K + lane] = v;
        }
    }
}

// ---------------------------------------------------------------------------
extern "C" void kernel_launch(void* const* d_in, const int* in_sizes, int n_in,
                              void* d_out, int out_size) {
    const int*   words = (const int*)d_in[0];     // [T,B,F] int32
    const int*   lens  = (const int*)d_in[1];     // [B] int32
    const float* W     = (const float*)d_in[2];   // [1e6] f32
    const float* trans = (const float*)d_in[3];   // [K,K] f32
    float* out   = (float*)d_out;
    float* score = out + OFF_SCORE;
    float* maxs  = out + OFF_MAXS;
    float* idxo  = out + OFF_IDX;
    float* feats = out + OFF_FEATS;

    feats_kernel<<<(T * B) / 8, 256>>>(words, lens, W, feats, maxs, idxo);
    rec_kernel<<<B, 128>>>(trans, lens, feats, maxs, idxo, score);
}